// round 1
// baseline (speedup 1.0000x reference)
#include <cuda_runtime.h>
#include <cuda_bf16.h>
#include <cstdint>

#define NPTS     16384
#define TPB      256
#define PBLOCKS  (NPTS / TPB)      // 64
#define QSPLITS  8
#define QCHUNK   (NPTS / QSPLITS)  // 2048 points per block
#define PAIRSTEPS_PER_CHUNK (QCHUNK / 2)   // 1024
#define ENTRIES_PER_CHUNK   (QCHUNK)       // 2048 ulonglong2 entries (2 per pair-step)

// ---------------------------------------------------------------------------
// Device scratch (static; no allocations anywhere).
// g_plain[s][i] = (p0, p1, p2, |p|^2) for set s (0 = transformed moving, 1 = fixed)
// g_pair[s]     = pair-interleaved records for set s used when s is the "inner" set:
//                 entry[2t]   = { pack(q0_{2t}, q0_{2t+1}), pack(q1_{2t}, q1_{2t+1}) }
//                 entry[2t+1] = { pack(q2_{2t}, q2_{2t+1}), pack(c_{2t},  c_{2t+1})  }
//                 with c = -0.5 * |q|^2
// ---------------------------------------------------------------------------
__device__ float4      g_plain[2][NPTS];
__device__ ulonglong2  g_pair[2][NPTS];
__device__ float       g_partial[2][QSPLITS * NPTS];

// ---------------- f32x2 helpers ----------------
__device__ __forceinline__ unsigned long long pack2(float lo, float hi) {
    return ((unsigned long long)__float_as_uint(hi) << 32) | (unsigned long long)__float_as_uint(lo);
}
__device__ __forceinline__ unsigned long long splat2(float v) {
    unsigned long long r;
    asm("mov.b64 %0, {%1, %1};" : "=l"(r) : "f"(v));
    return r;
}
__device__ __forceinline__ unsigned long long fma2(unsigned long long a, unsigned long long b,
                                                   unsigned long long c) {
    unsigned long long d;
    asm("fma.rn.f32x2 %0, %1, %2, %3;" : "=l"(d) : "l"(a), "l"(b), "l"(c));
    return d;
}
__device__ __forceinline__ void unpack2(unsigned long long v, float& lo, float& hi) {
    asm("mov.b64 {%0, %1}, %2;" : "=f"(lo), "=f"(hi) : "l"(v));
}

__device__ __forceinline__ float neg_inf_f() { return __int_as_float(0xff800000); }

// ---------------------------------------------------------------------------
// prep: affine-transform moving points, build plain + pair-interleaved buffers,
// zero the output scalar.
// ---------------------------------------------------------------------------
__device__ __forceinline__ float3 xform_mov(const float* __restrict__ mv, int i,
                                            const float* __restrict__ mat,
                                            const float* __restrict__ tr) {
    float m0 = mv[3 * i + 0], m1 = mv[3 * i + 1], m2 = mv[3 * i + 2];
    float3 x;
    x.x = fmaf(m0, mat[0], fmaf(m1, mat[3], fmaf(m2, mat[6], tr[0])));
    x.y = fmaf(m0, mat[1], fmaf(m1, mat[4], fmaf(m2, mat[7], tr[1])));
    x.z = fmaf(m0, mat[2], fmaf(m1, mat[5], fmaf(m2, mat[8], tr[2])));
    return x;
}

__global__ void prep_kernel(const float* __restrict__ fx, const float* __restrict__ mv,
                            const float* __restrict__ mat, const float* __restrict__ tr,
                            float* __restrict__ out) {
    int i = blockIdx.x * blockDim.x + threadIdx.x;
    if (i == 0) out[0] = 0.0f;

    if (i < NPTS) {
        float3 x = xform_mov(mv, i, mat, tr);
        float x2 = fmaf(x.x, x.x, fmaf(x.y, x.y, x.z * x.z));
        g_plain[0][i] = make_float4(x.x, x.y, x.z, x2);

        float3 y = make_float3(fx[3 * i + 0], fx[3 * i + 1], fx[3 * i + 2]);
        float y2 = fmaf(y.x, y.x, fmaf(y.y, y.y, y.z * y.z));
        g_plain[1][i] = make_float4(y.x, y.y, y.z, y2);
    }
    if (i < NPTS / 2) {
        int ja = 2 * i, jb = 2 * i + 1;
        // set 0 (moving, transformed)
        {
            float3 a = xform_mov(mv, ja, mat, tr);
            float3 b = xform_mov(mv, jb, mat, tr);
            float ca = -0.5f * fmaf(a.x, a.x, fmaf(a.y, a.y, a.z * a.z));
            float cb = -0.5f * fmaf(b.x, b.x, fmaf(b.y, b.y, b.z * b.z));
            ulonglong2 e0, e1;
            e0.x = pack2(a.x, b.x);  e0.y = pack2(a.y, b.y);
            e1.x = pack2(a.z, b.z);  e1.y = pack2(ca, cb);
            g_pair[0][2 * i]     = e0;
            g_pair[0][2 * i + 1] = e1;
        }
        // set 1 (fixed)
        {
            float3 a = make_float3(fx[3 * ja + 0], fx[3 * ja + 1], fx[3 * ja + 2]);
            float3 b = make_float3(fx[3 * jb + 0], fx[3 * jb + 1], fx[3 * jb + 2]);
            float ca = -0.5f * fmaf(a.x, a.x, fmaf(a.y, a.y, a.z * a.z));
            float cb = -0.5f * fmaf(b.x, b.x, fmaf(b.y, b.y, b.z * b.z));
            ulonglong2 e0, e1;
            e0.x = pack2(a.x, b.x);  e0.y = pack2(a.y, b.y);
            e1.x = pack2(a.z, b.z);  e1.y = pack2(ca, cb);
            g_pair[1][2 * i]     = e0;
            g_pair[1][2 * i + 1] = e1;
        }
    }
}

// ---------------------------------------------------------------------------
// dir: for direction d, P = g_plain[d], Q = g_pair[d^1].
// Block (bx, qs): threads own P points [bx*256, bx*256+256); sweep Q chunk qs.
// Writes per-split partial max of s = p.q - |q|^2/2 into g_partial[d].
// ---------------------------------------------------------------------------
__global__ void __launch_bounds__(TPB) dir_kernel(int dir) {
    __shared__ ulonglong2 tile[ENTRIES_PER_CHUNK];   // 32 KB

    int qs = blockIdx.y;
    const ulonglong2* __restrict__ src = &g_pair[dir ^ 1][qs * ENTRIES_PER_CHUNK];
    #pragma unroll 2
    for (int i = threadIdx.x; i < ENTRIES_PER_CHUNK; i += TPB) tile[i] = src[i];
    __syncthreads();

    int ip = blockIdx.x * TPB + threadIdx.x;
    float4 P = g_plain[dir][ip];
    unsigned long long px = splat2(P.x);
    unsigned long long py = splat2(P.y);
    unsigned long long pz = splat2(P.z);

    float m0 = neg_inf_f(), m1 = neg_inf_f();
    float m2 = neg_inf_f(), m3 = neg_inf_f();

    #pragma unroll 4
    for (int t = 0; t < PAIRSTEPS_PER_CHUNK; t += 2) {
        ulonglong2 v1a = tile[2 * t + 0];
        ulonglong2 v2a = tile[2 * t + 1];
        ulonglong2 v1b = tile[2 * t + 2];
        ulonglong2 v2b = tile[2 * t + 3];

        unsigned long long acca = fma2(px, v1a.x, v2a.y);
        unsigned long long accb = fma2(px, v1b.x, v2b.y);
        acca = fma2(py, v1a.y, acca);
        accb = fma2(py, v1b.y, accb);
        acca = fma2(pz, v2a.x, acca);
        accb = fma2(pz, v2b.x, accb);

        float la, ha, lb, hb;
        unpack2(acca, la, ha);
        unpack2(accb, lb, hb);
        m0 = fmaxf(m0, la);
        m1 = fmaxf(m1, ha);
        m2 = fmaxf(m2, lb);
        m3 = fmaxf(m3, hb);
    }
    float m = fmaxf(fmaxf(m0, m1), fmaxf(m2, m3));
    g_partial[dir][qs * NPTS + ip] = m;
}

// ---------------------------------------------------------------------------
// combine: fold the QSPLITS partial maxes, form min-d2, reduce mean, add to out.
// ---------------------------------------------------------------------------
__global__ void __launch_bounds__(TPB) combine_kernel(int dir, float* __restrict__ out) {
    __shared__ float wsum[TPB / 32];
    int ip = blockIdx.x * TPB + threadIdx.x;

    float m = neg_inf_f();
    #pragma unroll
    for (int s = 0; s < QSPLITS; s++) m = fmaxf(m, g_partial[dir][s * NPTS + ip]);

    float d2 = fmaf(-2.0f, m, g_plain[dir][ip].w);
    d2 = fmaxf(d2, 0.0f);

    // warp reduce
    #pragma unroll
    for (int off = 16; off > 0; off >>= 1)
        d2 += __shfl_down_sync(0xffffffffu, d2, off);

    int lane = threadIdx.x & 31, warp = threadIdx.x >> 5;
    if (lane == 0) wsum[warp] = d2;
    __syncthreads();
    if (warp == 0) {
        float v = (lane < TPB / 32) ? wsum[lane] : 0.0f;
        #pragma unroll
        for (int off = 4; off > 0; off >>= 1)
            v += __shfl_down_sync(0xffffffffu, v, off);
        if (lane == 0) atomicAdd(out, v * (1.0f / (float)NPTS));
    }
}

// ---------------------------------------------------------------------------
// Launch. Inputs (metadata order): pts_fixed [16384*3], pts_mov [16384*3],
// mat [9], trans [3]. Output: 1 float.
// ---------------------------------------------------------------------------
extern "C" void kernel_launch(void* const* d_in, const int* in_sizes, int n_in,
                              void* d_out, int out_size) {
    const float* fx  = (const float*)d_in[0];
    const float* mv  = (const float*)d_in[1];
    const float* mat = (const float*)d_in[2];
    const float* tr  = (const float*)d_in[3];
    float* out = (float*)d_out;

    prep_kernel<<<PBLOCKS, TPB>>>(fx, mv, mat, tr, out);

    dim3 grid(PBLOCKS, QSPLITS);
    dir_kernel<<<grid, TPB>>>(0);   // moving -> fixed
    dir_kernel<<<grid, TPB>>>(1);   // fixed  -> moving

    combine_kernel<<<PBLOCKS, TPB>>>(0, out);
    combine_kernel<<<PBLOCKS, TPB>>>(1, out);
}

// round 2
// speedup vs baseline: 1.7200x; 1.7200x over previous
#include <cuda_runtime.h>
#include <cuda_bf16.h>
#include <cstdint>

#define NPTS        16384
#define TPB         256
#define PPT         4                       // P points per thread
#define P_PER_BLOCK (TPB * PPT)             // 1024
#define PBLK        (NPTS / P_PER_BLOCK)    // 16 P-blocks
#define QCHUNK      128                     // Q points per item (2 KB tile)
#define QSPL        (NPTS / QCHUNK)         // 128 Q chunks
#define ITEMS_PER_DIR (PBLK * QSPL)         // 2048
#define TOTAL_ITEMS (2 * ITEMS_PER_DIR)     // 4096
#define GRID_DIR    592                     // 148 SMs * 4 resident blocks

// ---------------------------------------------------------------------------
// Static device scratch (no allocations anywhere).
// g_p[s][i] = (x, y, z, |p|^2)   -- outer-loop records for set s
// g_q[s][i] = (x, y, z, -|q|^2/2) -- inner-loop records for set s
// g_best[d][i] = monotonic-uint encoding of max_j (p_i . q_j - |q_j|^2/2)
// ---------------------------------------------------------------------------
__device__ float4   g_p[2][NPTS];
__device__ float4   g_q[2][NPTS];
__device__ unsigned g_best[2][NPTS];
__device__ unsigned g_ticket;

// Monotonic float<->uint encoding: preserves total order under unsigned max.
__device__ __forceinline__ unsigned enc_f(float f) {
    unsigned u = __float_as_uint(f);
    return ((int)u < 0) ? ~u : (u | 0x80000000u);
}
__device__ __forceinline__ float dec_f(unsigned u) {
    unsigned b = (u & 0x80000000u) ? (u & 0x7fffffffu) : ~u;
    return __uint_as_float(b);
}

// ---------------------------------------------------------------------------
// prep: affine-transform moving points, build outer/inner records, reset
// best-buffers, ticket, and output scalar.
// ---------------------------------------------------------------------------
__device__ __forceinline__ float3 xform_mov(const float* __restrict__ mv, int i,
                                            const float* __restrict__ mat,
                                            const float* __restrict__ tr) {
    float m0 = mv[3 * i + 0], m1 = mv[3 * i + 1], m2 = mv[3 * i + 2];
    float3 x;
    x.x = fmaf(m0, mat[0], fmaf(m1, mat[3], fmaf(m2, mat[6], tr[0])));
    x.y = fmaf(m0, mat[1], fmaf(m1, mat[4], fmaf(m2, mat[7], tr[1])));
    x.z = fmaf(m0, mat[2], fmaf(m1, mat[5], fmaf(m2, mat[8], tr[2])));
    return x;
}

__global__ void __launch_bounds__(TPB) prep_kernel(
    const float* __restrict__ fx, const float* __restrict__ mv,
    const float* __restrict__ mat, const float* __restrict__ tr,
    float* __restrict__ out) {
    int i = blockIdx.x * TPB + threadIdx.x;
    if (i == 0) { out[0] = 0.0f; g_ticket = 0u; }
    if (i >= NPTS) return;

    float3 x = xform_mov(mv, i, mat, tr);
    float x2 = fmaf(x.x, x.x, fmaf(x.y, x.y, x.z * x.z));
    g_p[0][i] = make_float4(x.x, x.y, x.z, x2);
    g_q[0][i] = make_float4(x.x, x.y, x.z, -0.5f * x2);

    float3 y = make_float3(fx[3 * i + 0], fx[3 * i + 1], fx[3 * i + 2]);
    float y2 = fmaf(y.x, y.x, fmaf(y.y, y.y, y.z * y.z));
    g_p[1][i] = make_float4(y.x, y.y, y.z, y2);
    g_q[1][i] = make_float4(y.x, y.y, y.z, -0.5f * y2);

    g_best[0][i] = 0u;
    g_best[1][i] = 0u;
}

// ---------------------------------------------------------------------------
// dir: persistent blocks pop (dir, pblk, qchunk) items off a global ticket.
// Each item: cache QCHUNK inner points in smem, sweep them against PPT outer
// points per thread (3 FFMA + amortized 1 FMNMX per pair), flush running max
// via RED.MAX.U32 on the encoded value.
// ---------------------------------------------------------------------------
__global__ void __launch_bounds__(TPB, 4) dir_kernel() {
    __shared__ float4   tile[QCHUNK];   // 2 KB
    __shared__ unsigned s_item;
    const int tid = threadIdx.x;

    for (;;) {
        __syncthreads();                       // protect tile/s_item from prev iter
        if (tid == 0) s_item = atomicAdd(&g_ticket, 1u);
        __syncthreads();
        unsigned it = s_item;
        if (it >= TOTAL_ITEMS) return;

        int dir  = (int)(it >> 11);            // / ITEMS_PER_DIR
        int pblk = (int)(it >> 7) & (PBLK - 1);
        int qc   = (int)it & (QSPL - 1);

        if (tid < QCHUNK) tile[tid] = g_q[dir ^ 1][qc * QCHUNK + tid];

        int pbase = pblk * P_PER_BLOCK + tid;
        float3 P[PPT];
        float  m[PPT];
        #pragma unroll
        for (int k = 0; k < PPT; k++) {
            float4 t = g_p[dir][pbase + k * TPB];
            P[k] = make_float3(t.x, t.y, t.z);
            m[k] = __int_as_float(0xff800000);  // -inf
        }
        __syncthreads();

        #pragma unroll 2
        for (int j = 0; j < QCHUNK; j += 2) {
            float4 qa = tile[j];
            float4 qb = tile[j + 1];
            #pragma unroll
            for (int k = 0; k < PPT; k++) {
                float sa = fmaf(P[k].x, qa.x, qa.w);
                sa = fmaf(P[k].y, qa.y, sa);
                sa = fmaf(P[k].z, qa.z, sa);
                float sb = fmaf(P[k].x, qb.x, qb.w);
                sb = fmaf(P[k].y, qb.y, sb);
                sb = fmaf(P[k].z, qb.z, sb);
                m[k] = fmaxf(m[k], fmaxf(sa, sb));
            }
        }

        #pragma unroll
        for (int k = 0; k < PPT; k++)
            atomicMax(&g_best[dir][pbase + k * TPB], enc_f(m[k]));
    }
}

// ---------------------------------------------------------------------------
// combine: decode best, form min-d2, clamp, reduce mean per direction into out.
// ---------------------------------------------------------------------------
__global__ void __launch_bounds__(TPB) combine_kernel(float* __restrict__ out) {
    __shared__ float wsum[TPB / 32];
    int dir = blockIdx.y;
    int i = blockIdx.x * TPB + threadIdx.x;

    float mbest = dec_f(g_best[dir][i]);
    float d2 = fmaf(-2.0f, mbest, g_p[dir][i].w);
    d2 = fmaxf(d2, 0.0f);

    #pragma unroll
    for (int off = 16; off > 0; off >>= 1)
        d2 += __shfl_down_sync(0xffffffffu, d2, off);

    int lane = threadIdx.x & 31, warp = threadIdx.x >> 5;
    if (lane == 0) wsum[warp] = d2;
    __syncthreads();
    if (warp == 0) {
        float v = (lane < TPB / 32) ? wsum[lane] : 0.0f;
        #pragma unroll
        for (int off = 4; off > 0; off >>= 1)
            v += __shfl_down_sync(0xffffffffu, v, off);
        if (lane == 0) atomicAdd(out, v * (1.0f / (float)NPTS));
    }
}

// ---------------------------------------------------------------------------
// Launch. Inputs (metadata order): pts_fixed [16384*3], pts_mov [16384*3],
// mat [9], trans [3]. Output: 1 float.
// ---------------------------------------------------------------------------
extern "C" void kernel_launch(void* const* d_in, const int* in_sizes, int n_in,
                              void* d_out, int out_size) {
    const float* fx  = (const float*)d_in[0];
    const float* mv  = (const float*)d_in[1];
    const float* mat = (const float*)d_in[2];
    const float* tr  = (const float*)d_in[3];
    float* out = (float*)d_out;

    prep_kernel<<<NPTS / TPB, TPB>>>(fx, mv, mat, tr, out);
    dir_kernel<<<GRID_DIR, TPB>>>();
    combine_kernel<<<dim3(NPTS / TPB, 2), TPB>>>(out);
}